// round 1
// baseline (speedup 1.0000x reference)
#include <cuda_runtime.h>
#include <cstdint>

// Problem dims (fixed by the benchmark)
#define B_DIM 8
#define C_DIM 256
#define N_TOK 1024           // text tokens
#define M_PIX 9216           // 96*96
#define L_DIM 2048           // B*C
#define TEXT_B_STRIDE  262144    // 1024*256
#define IMG_B_STRIDE   2359296   // 256*9216

#define NITER 50
// EPSILON = 0.1 ; K = exp(-cost/eps) = exp(-10*cost) ; T = exp(-cost*eps)=exp(-0.1*cost)
#define CONV_TOL_SQ 1e-4f    // (0.01)^2
#define DENOM_SHIFT 100.0f

// ---------------- device scratch (no mallocs allowed) ----------------
__device__ float g_cost[(size_t)N_TOK * M_PIX];  // 37.75 MB; becomes T in-place
__device__ float g_sqA[N_TOK];
__device__ float g_sqB[M_PIX];
__device__ float g_u[N_TOK];
__device__ float g_v[M_PIX];
__device__ float g_normU[64];
__device__ float g_normV[64];
__device__ unsigned g_bar_count;
__device__ unsigned g_bar_gen;

// ---------------- init (runs every launch; graph-replay safe) ----------------
__global__ void k_init() {
    int tid = blockIdx.x * blockDim.x + threadIdx.x;
    if (tid < N_TOK) g_u[tid] = 1.0f;
    if (tid < M_PIX) { g_v[tid] = 1.0f; g_sqB[tid] = 0.0f; }
    if (tid < 64) { g_normU[tid] = 0.0f; g_normV[tid] = 0.0f; }
    if (tid == 0) { g_bar_count = 0u; g_bar_gen = 0u; }
}

// ---------------- squared norms ----------------
__global__ void k_sq_text(const float* __restrict__ text) {
    __shared__ float sh[256];
    int n = blockIdx.x;
    int c = threadIdx.x; // 256 threads, one per channel
    float s = 0.0f;
#pragma unroll
    for (int b = 0; b < B_DIM; ++b) {
        float x = text[(size_t)b * TEXT_B_STRIDE + (size_t)n * C_DIM + c];
        s += x * x;
    }
    sh[c] = s; __syncthreads();
    for (int off = 128; off > 0; off >>= 1) {
        if (c < off) sh[c] += sh[c + off];
        __syncthreads();
    }
    if (c == 0) g_sqA[n] = sh[0];
}

__global__ void k_sq_image(const float* __restrict__ image) {
    int m = blockIdx.x * 256 + threadIdx.x;     // grid.x = 36
    int l0 = blockIdx.y * 256;                  // grid.y = 8
    float s = 0.0f;
    for (int l = l0; l < l0 + 256; ++l) {
        float x = image[(size_t)l * M_PIX + m];
        s += x * x;
    }
    atomicAdd(&g_sqB[m], s);
}

// ---------------- GEMM common config ----------------
#define BM 128
#define BN 128
#define BK 16
// 256 threads, 16x16 thread grid, 8x8 micro-tile

// GEMM1: cost[n,m] = sqrt(max(sqA[n]+sqB[m]-2*sum_l A[l,n]*Bf[l,m], 1e-12))
// A[l,n] = text[b,n,c] (l=b*256+c) ; Bf[l,m] = image[b,c,m]
__global__ void k_gemm1_cost(const float* __restrict__ text,
                             const float* __restrict__ image) {
    __shared__ float As[BK][BM];  // [l][n]
    __shared__ float Bs[BK][BN];  // [l][m]
    const int tid = threadIdx.x;
    const int ty = tid >> 4, tx = tid & 15;
    const int m0 = blockIdx.x * BN;   // 72 tiles
    const int n0 = blockIdx.y * BM;   // 8 tiles
    float acc[8][8] = {};
    for (int kt = 0; kt < L_DIM; kt += BK) {
        const int bb = kt >> 8, cc0 = kt & 255;
        const float* tbase = text + (size_t)bb * TEXT_B_STRIDE + cc0;
#pragma unroll
        for (int it = 0; it < 2; ++it) {
            int lin = tid + it * 256;
            int row = lin >> 2, q = lin & 3;
            float4 v = *(const float4*)(tbase + (size_t)(n0 + row) * C_DIM + q * 4);
            As[q * 4 + 0][row] = v.x; As[q * 4 + 1][row] = v.y;
            As[q * 4 + 2][row] = v.z; As[q * 4 + 3][row] = v.w;
        }
        const float* ibase = image + (size_t)bb * IMG_B_STRIDE + (size_t)cc0 * M_PIX + m0;
#pragma unroll
        for (int it = 0; it < 2; ++it) {
            int lin = tid + it * 256;
            int dl = lin >> 5, q = lin & 31;
            float4 v = *(const float4*)(ibase + (size_t)dl * M_PIX + q * 4);
            *(float4*)&Bs[dl][q * 4] = v;
        }
        __syncthreads();
#pragma unroll
        for (int k = 0; k < BK; ++k) {
            float ra[8], rb[8];
#pragma unroll
            for (int i = 0; i < 8; ++i) ra[i] = As[k][ty * 8 + i];
#pragma unroll
            for (int j = 0; j < 8; ++j) rb[j] = Bs[k][tx * 8 + j];
#pragma unroll
            for (int i = 0; i < 8; ++i)
#pragma unroll
                for (int j = 0; j < 8; ++j)
                    acc[i][j] = fmaf(ra[i], rb[j], acc[i][j]);
        }
        __syncthreads();
    }
    // epilogue: cost
#pragma unroll
    for (int i = 0; i < 8; ++i) {
        int n = n0 + ty * 8 + i;
        float sa = g_sqA[n];
        float out[8];
#pragma unroll
        for (int j = 0; j < 8; ++j) {
            int m = m0 + tx * 8 + j;
            float sq = sa + g_sqB[m] - 2.0f * acc[i][j];
            out[j] = sqrtf(fmaxf(sq, 1e-12f));
        }
        float* p = g_cost + (size_t)n * M_PIX + m0 + tx * 8;
        *(float4*)p = make_float4(out[0], out[1], out[2], out[3]);
        *(float4*)(p + 4) = make_float4(out[4], out[5], out[6], out[7]);
    }
}

// ---------------- Sinkhorn: one persistent kernel, software grid barrier ----------------
__device__ __forceinline__ void grid_barrier(unsigned e, int nctas) {
    __syncthreads();
    if (threadIdx.x == 0) {
        __threadfence();
        unsigned t = atomicAdd(&g_bar_count, 1u) + 1u;
        if (t == (unsigned)nctas * e) {
            atomicExch(&g_bar_gen, e);
        } else {
            while (*((volatile unsigned*)&g_bar_gen) < e) __nanosleep(64);
        }
        __threadfence();
    }
    __syncthreads();
}

__global__ void k_sinkhorn() {
    __shared__ float sred[256];
    const int cta = blockIdx.x;
    const int tid = threadIdx.x;
    const int NC = gridDim.x;  // 148, all resident
    unsigned epoch = 0;
    for (int it = 0; it < NITER; ++it) {
        // ---- phase U: un = 1/(sum_m K[n,m]*v[m] + 100) ----
        for (int n = cta; n < N_TOK; n += NC) {
            const float* row = g_cost + (size_t)n * M_PIX;
            float s = 0.0f;
            for (int m = tid; m < M_PIX; m += 256)
                s += __expf(-10.0f * row[m]) * __ldcg(&g_v[m]);
            sred[tid] = s; __syncthreads();
            for (int off = 128; off > 0; off >>= 1) {
                if (tid < off) sred[tid] += sred[tid + off];
                __syncthreads();
            }
            if (tid == 0) {
                float un = 1.0f / (sred[0] + DENOM_SHIFT);
                float d = un - g_u[n];
                atomicAdd(&g_normU[it], d * d);
                g_u[n] = un;
            }
            __syncthreads();
        }
        ++epoch; grid_barrier(epoch, NC);
        // ---- phase V: vn = 1/(sum_n K[n,m]*u[n] + 100) ----
        for (int blk = cta; blk < (M_PIX / 64); blk += NC) {   // 144 column blocks of 64
            int col0 = blk * 64;
            int c = tid & 63, sl = tid >> 6;
            float t = 0.0f;
            for (int n = sl; n < N_TOK; n += 4)
                t += __expf(-10.0f * g_cost[(size_t)n * M_PIX + col0 + c]) * __ldcg(&g_u[n]);
            sred[tid] = t; __syncthreads();
            if (tid < 64) {
                float tt = sred[tid] + sred[tid + 64] + sred[tid + 128] + sred[tid + 192];
                int m = col0 + tid;
                float vn = 1.0f / (tt + DENOM_SHIFT);
                float d = vn - g_v[m];
                atomicAdd(&g_normV[it], d * d);
                g_v[m] = vn;
            }
            __syncthreads();
        }
        ++epoch; grid_barrier(epoch, NC);
        // ---- convergence: identical decision on all CTAs ----
        float nu = __ldcg(&g_normU[it]);
        float nv = __ldcg(&g_normV[it]);
        if (nu < CONV_TOL_SQ && nv < CONV_TOL_SQ) break;   // == reference freeze
    }
}

// ---------------- T = exp(-0.1*cost) * u[n] * v[m]  (in-place over g_cost) ----------------
__global__ void k_make_T() {
    int n = blockIdx.y;                        // 1024
    int m = blockIdx.x * 256 + threadIdx.x;    // 36*256
    size_t i = (size_t)n * M_PIX + m;
    g_cost[i] = expf(-0.1f * g_cost[i]) * g_u[n] * g_v[m];
}

// GEMM2: aligned_text[b,n,c] = sum_m Bf[l,m]*T[n,m],  l = b*256+c
// thread-tile rows = n (ty), cols = l (tx)  -> c-contiguous stores
__global__ void k_gemm2_text(const float* __restrict__ image,
                             float* __restrict__ out_text) {
    __shared__ float As[BK][BM];  // T: [dm][n]
    __shared__ float Bs[BK][BN];  // Bf: [dm][l]
    const int tid = threadIdx.x;
    const int ty = tid >> 4, tx = tid & 15;
    const int l0 = blockIdx.x * BN;   // 16 tiles
    const int n0 = blockIdx.y * BM;   // 8 tiles
    const int bb = l0 >> 8, cc0 = l0 & 255;
    float acc[8][8] = {};
    for (int kt = 0; kt < M_PIX; kt += BK) {
#pragma unroll
        for (int it = 0; it < 2; ++it) {
            int lin = tid + it * 256;
            int row = lin >> 2, q = lin & 3;
            float4 v = *(const float4*)(g_cost + (size_t)(n0 + row) * M_PIX + kt + q * 4);
            As[q * 4 + 0][row] = v.x; As[q * 4 + 1][row] = v.y;
            As[q * 4 + 2][row] = v.z; As[q * 4 + 3][row] = v.w;
        }
#pragma unroll
        for (int it = 0; it < 2; ++it) {
            int lin = tid + it * 256;
            int row = lin >> 2, q = lin & 3;  // row = l offset in tile
            float4 v = *(const float4*)(image + (size_t)bb * IMG_B_STRIDE +
                                        (size_t)(cc0 + row) * M_PIX + kt + q * 4);
            Bs[q * 4 + 0][row] = v.x; Bs[q * 4 + 1][row] = v.y;
            Bs[q * 4 + 2][row] = v.z; Bs[q * 4 + 3][row] = v.w;
        }
        __syncthreads();
#pragma unroll
        for (int k = 0; k < BK; ++k) {
            float ra[8], rb[8];
#pragma unroll
            for (int i = 0; i < 8; ++i) ra[i] = As[k][ty * 8 + i];
#pragma unroll
            for (int j = 0; j < 8; ++j) rb[j] = Bs[k][tx * 8 + j];
#pragma unroll
            for (int i = 0; i < 8; ++i)
#pragma unroll
                for (int j = 0; j < 8; ++j)
                    acc[i][j] = fmaf(ra[i], rb[j], acc[i][j]);
        }
        __syncthreads();
    }
    const int ctile = cc0 + tx * 8;
#pragma unroll
    for (int i = 0; i < 8; ++i) {
        int n = n0 + ty * 8 + i;
        float* p = out_text + (size_t)bb * TEXT_B_STRIDE + (size_t)n * C_DIM + ctile;
        *(float4*)p = make_float4(acc[i][0], acc[i][1], acc[i][2], acc[i][3]);
        *(float4*)(p + 4) = make_float4(acc[i][4], acc[i][5], acc[i][6], acc[i][7]);
    }
}

// GEMM3: aligned_image[b,c,m] = sum_n A[l,n]*T[n,m],  A[l,n]=text[b,n,c]
// thread-tile rows = l (ty), cols = m (tx)
__global__ void k_gemm3_image(const float* __restrict__ text,
                              float* __restrict__ out_img) {
    __shared__ float As[BK][BM];  // A: [dn][l]
    __shared__ float Bs[BK][BN];  // T: [dn][m]
    const int tid = threadIdx.x;
    const int ty = tid >> 4, tx = tid & 15;
    const int m0 = blockIdx.x * BN;   // 72 tiles
    const int l0 = blockIdx.y * BM;   // 16 tiles
    const int bb = l0 >> 8, cc0 = l0 & 255;
    float acc[8][8] = {};
    for (int kt = 0; kt < N_TOK; kt += BK) {
#pragma unroll
        for (int it = 0; it < 2; ++it) {
            int lin = tid + it * 256;
            int dn = lin >> 5, q = lin & 31;
            float4 v = *(const float4*)(text + (size_t)bb * TEXT_B_STRIDE +
                                        (size_t)(kt + dn) * C_DIM + cc0 + q * 4);
            *(float4*)&As[dn][q * 4] = v;
        }
#pragma unroll
        for (int it = 0; it < 2; ++it) {
            int lin = tid + it * 256;
            int dn = lin >> 5, q = lin & 31;
            float4 v = *(const float4*)(g_cost + (size_t)(kt + dn) * M_PIX + m0 + q * 4);
            *(float4*)&Bs[dn][q * 4] = v;
        }
        __syncthreads();
#pragma unroll
        for (int k = 0; k < BK; ++k) {
            float ra[8], rb[8];
#pragma unroll
            for (int i = 0; i < 8; ++i) ra[i] = As[k][ty * 8 + i];
#pragma unroll
            for (int j = 0; j < 8; ++j) rb[j] = Bs[k][tx * 8 + j];
#pragma unroll
            for (int i = 0; i < 8; ++i)
#pragma unroll
                for (int j = 0; j < 8; ++j)
                    acc[i][j] = fmaf(ra[i], rb[j], acc[i][j]);
        }
        __syncthreads();
    }
#pragma unroll
    for (int i = 0; i < 8; ++i) {
        int c = cc0 + ty * 8 + i;
        float* p = out_img + (size_t)bb * IMG_B_STRIDE + (size_t)c * M_PIX + m0 + tx * 8;
        *(float4*)p = make_float4(acc[i][0], acc[i][1], acc[i][2], acc[i][3]);
        *(float4*)(p + 4) = make_float4(acc[i][4], acc[i][5], acc[i][6], acc[i][7]);
    }
}

// ---------------- launch ----------------
extern "C" void kernel_launch(void* const* d_in, const int* in_sizes, int n_in,
                              void* d_out, int out_size) {
    const float* text  = (const float*)d_in[0];   // [8,1024,256]
    const float* image = (const float*)d_in[1];   // [8,256,96,96]
    float* out_text = (float*)d_out;                       // [8,1024,256]
    float* out_img  = out_text + (size_t)B_DIM * N_TOK * C_DIM;  // [8,256,96,96]

    k_init<<<36, 256>>>();
    k_sq_text<<<N_TOK, 256>>>(text);
    k_sq_image<<<dim3(M_PIX / 256, L_DIM / 256), 256>>>(image);
    k_gemm1_cost<<<dim3(M_PIX / BN, N_TOK / BM), 256>>>(text, image);
    k_sinkhorn<<<148, 256>>>();
    k_make_T<<<dim3(M_PIX / 256, N_TOK), 256>>>();
    k_gemm2_text<<<dim3(L_DIM / BN, N_TOK / BM), 256>>>(image, out_text);
    k_gemm3_image<<<dim3(M_PIX / BN, L_DIM / BM), 256>>>(text, out_img);
}

// round 2
// speedup vs baseline: 1.0001x; 1.0001x over previous
#include <cuda_runtime.h>
#include <cstdint>

// Problem dims (fixed by the benchmark)
#define B_DIM 8
#define C_DIM 256
#define N_TOK 1024           // text tokens
#define M_PIX 9216           // 96*96
#define L_DIM 2048           // B*C
#define TEXT_B_STRIDE  262144    // 1024*256
#define IMG_B_STRIDE   2359296   // 256*9216

#define NITER 50
// EPSILON = 0.1 ; K = exp(-cost/eps) = exp(-10*cost) ; T = exp(-cost*eps)=exp(-0.1*cost)
#define CONV_TOL_SQ 1e-4f    // (0.01)^2
#define DENOM_SHIFT 100.0f

// ---------------- device scratch (no mallocs allowed) ----------------
__device__ float g_cost[(size_t)N_TOK * M_PIX];  // 37.75 MB; becomes T in-place
__device__ float g_sqA[N_TOK];
__device__ float g_sqB[M_PIX];
__device__ float g_u[N_TOK];
__device__ float g_v[M_PIX];
__device__ float g_normU[64];
__device__ float g_normV[64];
__device__ unsigned g_bar_count;
__device__ unsigned g_bar_gen;

// ---------------- init (runs every launch; graph-replay safe) ----------------
__global__ void k_init() {
    int tid = blockIdx.x * blockDim.x + threadIdx.x;
    if (tid < N_TOK) g_u[tid] = 1.0f;
    if (tid < M_PIX) { g_v[tid] = 1.0f; g_sqB[tid] = 0.0f; }
    if (tid < 64) { g_normU[tid] = 0.0f; g_normV[tid] = 0.0f; }
    if (tid == 0) { g_bar_count = 0u; g_bar_gen = 0u; }
}

// ---------------- squared norms ----------------
__global__ void k_sq_text(const float* __restrict__ text) {
    __shared__ float sh[256];
    int n = blockIdx.x;
    int c = threadIdx.x; // 256 threads, one per channel
    float s = 0.0f;
#pragma unroll
    for (int b = 0; b < B_DIM; ++b) {
        float x = text[(size_t)b * TEXT_B_STRIDE + (size_t)n * C_DIM + c];
        s += x * x;
    }
    sh[c] = s; __syncthreads();
    for (int off = 128; off > 0; off >>= 1) {
        if (c < off) sh[c] += sh[c + off];
        __syncthreads();
    }
    if (c == 0) g_sqA[n] = sh[0];
}

__global__ void k_sq_image(const float* __restrict__ image) {
    int m = blockIdx.x * 256 + threadIdx.x;     // grid.x = 36
    int l0 = blockIdx.y * 256;                  // grid.y = 8
    float s = 0.0f;
    for (int l = l0; l < l0 + 256; ++l) {
        float x = image[(size_t)l * M_PIX + m];
        s += x * x;
    }
    atomicAdd(&g_sqB[m], s);
}

// ---------------- GEMM common config ----------------
#define BM 128
#define BN 128
#define BK 16
// 256 threads, 16x16 thread grid, 8x8 micro-tile

// GEMM1: cost[n,m] = sqrt(max(sqA[n]+sqB[m]-2*sum_l A[l,n]*Bf[l,m], 1e-12))
// A[l,n] = text[b,n,c] (l=b*256+c) ; Bf[l,m] = image[b,c,m]
__global__ void k_gemm1_cost(const float* __restrict__ text,
                             const float* __restrict__ image) {
    __shared__ float As[BK][BM];  // [l][n]
    __shared__ float Bs[BK][BN];  // [l][m]
    const int tid = threadIdx.x;
    const int ty = tid >> 4, tx = tid & 15;
    const int m0 = blockIdx.x * BN;   // 72 tiles
    const int n0 = blockIdx.y * BM;   // 8 tiles
    float acc[8][8] = {};
    for (int kt = 0; kt < L_DIM; kt += BK) {
        const int bb = kt >> 8, cc0 = kt & 255;
        const float* tbase = text + (size_t)bb * TEXT_B_STRIDE + cc0;
#pragma unroll
        for (int it = 0; it < 2; ++it) {
            int lin = tid + it * 256;
            int row = lin >> 2, q = lin & 3;
            float4 v = *(const float4*)(tbase + (size_t)(n0 + row) * C_DIM + q * 4);
            As[q * 4 + 0][row] = v.x; As[q * 4 + 1][row] = v.y;
            As[q * 4 + 2][row] = v.z; As[q * 4 + 3][row] = v.w;
        }
        const float* ibase = image + (size_t)bb * IMG_B_STRIDE + (size_t)cc0 * M_PIX + m0;
#pragma unroll
        for (int it = 0; it < 2; ++it) {
            int lin = tid + it * 256;
            int dl = lin >> 5, q = lin & 31;
            float4 v = *(const float4*)(ibase + (size_t)dl * M_PIX + q * 4);
            *(float4*)&Bs[dl][q * 4] = v;
        }
        __syncthreads();
#pragma unroll
        for (int k = 0; k < BK; ++k) {
            float ra[8], rb[8];
#pragma unroll
            for (int i = 0; i < 8; ++i) ra[i] = As[k][ty * 8 + i];
#pragma unroll
            for (int j = 0; j < 8; ++j) rb[j] = Bs[k][tx * 8 + j];
#pragma unroll
            for (int i = 0; i < 8; ++i)
#pragma unroll
                for (int j = 0; j < 8; ++j)
                    acc[i][j] = fmaf(ra[i], rb[j], acc[i][j]);
        }
        __syncthreads();
    }
    // epilogue: cost
#pragma unroll
    for (int i = 0; i < 8; ++i) {
        int n = n0 + ty * 8 + i;
        float sa = g_sqA[n];
        float out[8];
#pragma unroll
        for (int j = 0; j < 8; ++j) {
            int m = m0 + tx * 8 + j;
            float sq = sa + g_sqB[m] - 2.0f * acc[i][j];
            out[j] = sqrtf(fmaxf(sq, 1e-12f));
        }
        float* p = g_cost + (size_t)n * M_PIX + m0 + tx * 8;
        *(float4*)p = make_float4(out[0], out[1], out[2], out[3]);
        *(float4*)(p + 4) = make_float4(out[4], out[5], out[6], out[7]);
    }
}

// ---------------- Sinkhorn: one persistent kernel, software grid barrier ----------------
__device__ __forceinline__ void grid_barrier(unsigned e, int nctas) {
    __syncthreads();
    if (threadIdx.x == 0) {
        __threadfence();
        unsigned t = atomicAdd(&g_bar_count, 1u) + 1u;
        if (t == (unsigned)nctas * e) {
            atomicExch(&g_bar_gen, e);
        } else {
            while (*((volatile unsigned*)&g_bar_gen) < e) __nanosleep(64);
        }
        __threadfence();
    }
    __syncthreads();
}

__global__ void k_sinkhorn() {
    __shared__ float sred[256];
    const int cta = blockIdx.x;
    const int tid = threadIdx.x;
    const int NC = gridDim.x;  // 148, all resident
    unsigned epoch = 0;
    for (int it = 0; it < NITER; ++it) {
        // ---- phase U: un = 1/(sum_m K[n,m]*v[m] + 100) ----
        for (int n = cta; n < N_TOK; n += NC) {
            const float* row = g_cost + (size_t)n * M_PIX;
            float s = 0.0f;
            for (int m = tid; m < M_PIX; m += 256)
                s += __expf(-10.0f * row[m]) * __ldcg(&g_v[m]);
            sred[tid] = s; __syncthreads();
            for (int off = 128; off > 0; off >>= 1) {
                if (tid < off) sred[tid] += sred[tid + off];
                __syncthreads();
            }
            if (tid == 0) {
                float un = 1.0f / (sred[0] + DENOM_SHIFT);
                float d = un - g_u[n];
                atomicAdd(&g_normU[it], d * d);
                g_u[n] = un;
            }
            __syncthreads();
        }
        ++epoch; grid_barrier(epoch, NC);
        // ---- phase V: vn = 1/(sum_n K[n,m]*u[n] + 100) ----
        for (int blk = cta; blk < (M_PIX / 64); blk += NC) {   // 144 column blocks of 64
            int col0 = blk * 64;
            int c = tid & 63, sl = tid >> 6;
            float t = 0.0f;
            for (int n = sl; n < N_TOK; n += 4)
                t += __expf(-10.0f * g_cost[(size_t)n * M_PIX + col0 + c]) * __ldcg(&g_u[n]);
            sred[tid] = t; __syncthreads();
            if (tid < 64) {
                float tt = sred[tid] + sred[tid + 64] + sred[tid + 128] + sred[tid + 192];
                int m = col0 + tid;
                float vn = 1.0f / (tt + DENOM_SHIFT);
                float d = vn - g_v[m];
                atomicAdd(&g_normV[it], d * d);
                g_v[m] = vn;
            }
            __syncthreads();
        }
        ++epoch; grid_barrier(epoch, NC);
        // ---- convergence: identical decision on all CTAs ----
        float nu = __ldcg(&g_normU[it]);
        float nv = __ldcg(&g_normV[it]);
        if (nu < CONV_TOL_SQ && nv < CONV_TOL_SQ) break;   // == reference freeze
    }
}

// ---------------- T = exp(-0.1*cost) * u[n] * v[m]  (in-place over g_cost) ----------------
__global__ void k_make_T() {
    int n = blockIdx.y;                        // 1024
    int m = blockIdx.x * 256 + threadIdx.x;    // 36*256
    size_t i = (size_t)n * M_PIX + m;
    g_cost[i] = expf(-0.1f * g_cost[i]) * g_u[n] * g_v[m];
}

// GEMM2: aligned_text[b,n,c] = sum_m Bf[l,m]*T[n,m],  l = b*256+c
// thread-tile rows = n (ty), cols = l (tx)  -> c-contiguous stores
__global__ void k_gemm2_text(const float* __restrict__ image,
                             float* __restrict__ out_text) {
    __shared__ float As[BK][BM];  // T: [dm][n]
    __shared__ float Bs[BK][BN];  // Bf: [dm][l]
    const int tid = threadIdx.x;
    const int ty = tid >> 4, tx = tid & 15;
    const int l0 = blockIdx.x * BN;   // 16 tiles
    const int n0 = blockIdx.y * BM;   // 8 tiles
    const int bb = l0 >> 8, cc0 = l0 & 255;
    float acc[8][8] = {};
    for (int kt = 0; kt < M_PIX; kt += BK) {
#pragma unroll
        for (int it = 0; it < 2; ++it) {
            int lin = tid + it * 256;
            int row = lin >> 2, q = lin & 3;
            float4 v = *(const float4*)(g_cost + (size_t)(n0 + row) * M_PIX + kt + q * 4);
            As[q * 4 + 0][row] = v.x; As[q * 4 + 1][row] = v.y;
            As[q * 4 + 2][row] = v.z; As[q * 4 + 3][row] = v.w;
        }
#pragma unroll
        for (int it = 0; it < 2; ++it) {
            int lin = tid + it * 256;
            int row = lin >> 2, q = lin & 3;  // row = l offset in tile
            float4 v = *(const float4*)(image + (size_t)bb * IMG_B_STRIDE +
                                        (size_t)(cc0 + row) * M_PIX + kt + q * 4);
            Bs[q * 4 + 0][row] = v.x; Bs[q * 4 + 1][row] = v.y;
            Bs[q * 4 + 2][row] = v.z; Bs[q * 4 + 3][row] = v.w;
        }
        __syncthreads();
#pragma unroll
        for (int k = 0; k < BK; ++k) {
            float ra[8], rb[8];
#pragma unroll
            for (int i = 0; i < 8; ++i) ra[i] = As[k][ty * 8 + i];
#pragma unroll
            for (int j = 0; j < 8; ++j) rb[j] = Bs[k][tx * 8 + j];
#pragma unroll
            for (int i = 0; i < 8; ++i)
#pragma unroll
                for (int j = 0; j < 8; ++j)
                    acc[i][j] = fmaf(ra[i], rb[j], acc[i][j]);
        }
        __syncthreads();
    }
    const int ctile = cc0 + tx * 8;
#pragma unroll
    for (int i = 0; i < 8; ++i) {
        int n = n0 + ty * 8 + i;
        float* p = out_text + (size_t)bb * TEXT_B_STRIDE + (size_t)n * C_DIM + ctile;
        *(float4*)p = make_float4(acc[i][0], acc[i][1], acc[i][2], acc[i][3]);
        *(float4*)(p + 4) = make_float4(acc[i][4], acc[i][5], acc[i][6], acc[i][7]);
    }
}

// GEMM3: aligned_image[b,c,m] = sum_n A[l,n]*T[n,m],  A[l,n]=text[b,n,c]
// thread-tile rows = l (ty), cols = m (tx)
__global__ void k_gemm3_image(const float* __restrict__ text,
                              float* __restrict__ out_img) {
    __shared__ float As[BK][BM];  // A: [dn][l]
    __shared__ float Bs[BK][BN];  // T: [dn][m]
    const int tid = threadIdx.x;
    const int ty = tid >> 4, tx = tid & 15;
    const int m0 = blockIdx.x * BN;   // 72 tiles
    const int l0 = blockIdx.y * BM;   // 16 tiles
    const int bb = l0 >> 8, cc0 = l0 & 255;
    float acc[8][8] = {};
    for (int kt = 0; kt < N_TOK; kt += BK) {
#pragma unroll
        for (int it = 0; it < 2; ++it) {
            int lin = tid + it * 256;
            int dn = lin >> 5, q = lin & 31;
            float4 v = *(const float4*)(text + (size_t)bb * TEXT_B_STRIDE +
                                        (size_t)(kt + dn) * C_DIM + cc0 + q * 4);
            *(float4*)&As[dn][q * 4] = v;
        }
#pragma unroll
        for (int it = 0; it < 2; ++it) {
            int lin = tid + it * 256;
            int dn = lin >> 5, q = lin & 31;
            float4 v = *(const float4*)(g_cost + (size_t)(kt + dn) * M_PIX + m0 + q * 4);
            *(float4*)&Bs[dn][q * 4] = v;
        }
        __syncthreads();
#pragma unroll
        for (int k = 0; k < BK; ++k) {
            float ra[8], rb[8];
#pragma unroll
            for (int i = 0; i < 8; ++i) ra[i] = As[k][ty * 8 + i];
#pragma unroll
            for (int j = 0; j < 8; ++j) rb[j] = Bs[k][tx * 8 + j];
#pragma unroll
            for (int i = 0; i < 8; ++i)
#pragma unroll
                for (int j = 0; j < 8; ++j)
                    acc[i][j] = fmaf(ra[i], rb[j], acc[i][j]);
        }
        __syncthreads();
    }
#pragma unroll
    for (int i = 0; i < 8; ++i) {
        int c = cc0 + ty * 8 + i;
        float* p = out_img + (size_t)bb * IMG_B_STRIDE + (size_t)c * M_PIX + m0 + tx * 8;
        *(float4*)p = make_float4(acc[i][0], acc[i][1], acc[i][2], acc[i][3]);
        *(float4*)(p + 4) = make_float4(acc[i][4], acc[i][5], acc[i][6], acc[i][7]);
    }
}

// ---------------- launch ----------------
extern "C" void kernel_launch(void* const* d_in, const int* in_sizes, int n_in,
                              void* d_out, int out_size) {
    const float* text  = (const float*)d_in[0];   // [8,1024,256]
    const float* image = (const float*)d_in[1];   // [8,256,96,96]
    float* out_text = (float*)d_out;                       // [8,1024,256]
    float* out_img  = out_text + (size_t)B_DIM * N_TOK * C_DIM;  // [8,256,96,96]

    k_init<<<36, 256>>>();
    k_sq_text<<<N_TOK, 256>>>(text);
    k_sq_image<<<dim3(M_PIX / 256, L_DIM / 256), 256>>>(image);
    k_gemm1_cost<<<dim3(M_PIX / BN, N_TOK / BM), 256>>>(text, image);
    k_sinkhorn<<<148, 256>>>();
    k_make_T<<<dim3(M_PIX / 256, N_TOK), 256>>>();
    k_gemm2_text<<<dim3(L_DIM / BN, N_TOK / BM), 256>>>(image, out_text);
    k_gemm3_image<<<dim3(M_PIX / BN, L_DIM / BM), 256>>>(text, out_img);
}